// round 1
// baseline (speedup 1.0000x reference)
#include <cuda_runtime.h>
#include <cstdint>

// ---------------------------------------------------------------------------
// DInPBlock: invo1 (32->64, s2) -> 5 dilated involutions -> concat -> bn+prelu
// Shapes: x (8,32,256,256) f32 ; out (8,320,128,128) f32
// ---------------------------------------------------------------------------

#define NBATCH 8

// Scratch (device globals; no runtime allocation allowed)
__device__ float g_xi[(size_t)NBATCH * 64 * 256 * 256];   // 33,554,432 f32 (134 MB)
__device__ float g_kmap1[(size_t)NBATCH * 9 * 128 * 128]; //  1,179,648 f32
__device__ float g_o1[(size_t)NBATCH * 64 * 128 * 128];   //  8,388,608 f32

// ---------------------------------------------------------------------------
// K1: xi = conv1x1(x, w1_init)  (8,32,256,256) -> (8,64,256,256)
// one thread per pixel, 64 accumulators, weights transposed [c][o] in smem
// ---------------------------------------------------------------------------
__global__ __launch_bounds__(256) void k_xi(const float* __restrict__ x,
                                            const float* __restrict__ w) {
    __shared__ float ws[32 * 64]; // ws[c*64+o] = w[o*32+c]
    for (int i = threadIdx.x; i < 2048; i += 256) {
        int o = i & 63, c = i >> 6;
        ws[i] = w[o * 32 + c];
    }
    __syncthreads();
    int p  = blockIdx.x * 256 + threadIdx.x;   // 0 .. 524287
    int hw = p & 65535;
    int b  = p >> 16;
    const float* xp = x + (size_t)b * 32 * 65536 + hw;
    float acc[64];
#pragma unroll
    for (int o = 0; o < 64; o++) acc[o] = 0.f;
#pragma unroll 4
    for (int c = 0; c < 32; c++) {
        float xv = __ldg(xp + (size_t)c * 65536);
        const float4* wp = (const float4*)(ws + c * 64);
#pragma unroll
        for (int o4 = 0; o4 < 16; o4++) {
            float4 wv = wp[o4];
            acc[4 * o4 + 0] = fmaf(xv, wv.x, acc[4 * o4 + 0]);
            acc[4 * o4 + 1] = fmaf(xv, wv.y, acc[4 * o4 + 1]);
            acc[4 * o4 + 2] = fmaf(xv, wv.z, acc[4 * o4 + 2]);
            acc[4 * o4 + 3] = fmaf(xv, wv.w, acc[4 * o4 + 3]);
        }
    }
    float* op = g_xi + (size_t)b * 64 * 65536 + hw;
#pragma unroll
    for (int o = 0; o < 64; o++) op[(size_t)o * 65536] = acc[o];
}

// ---------------------------------------------------------------------------
// K2: invo1 kernel map: avgpool2x2(x) -> conv 32->32 -> bn(1e-5)+relu -> 32->9
// output g_kmap1 (8,9,128,128)
// ---------------------------------------------------------------------------
__global__ __launch_bounds__(256) void k_kgen1(const float* __restrict__ x,
                                               const float* __restrict__ wred,
                                               const float* __restrict__ sg,
                                               const float* __restrict__ sb,
                                               const float* __restrict__ sm,
                                               const float* __restrict__ sv,
                                               const float* __restrict__ wspan) {
    __shared__ float wr[32 * 32]; // wr[c*32+o] = wred[o*32+c]
    __shared__ float wsp[9 * 32];
    __shared__ float ssc[32], sbi[32];
    for (int i = threadIdx.x; i < 1024; i += 256) {
        int o = i & 31, c = i >> 5;
        wr[i] = wred[o * 32 + c];
    }
    for (int i = threadIdx.x; i < 288; i += 256) wsp[i] = wspan[i];
    if (threadIdx.x < 32) {
        int o = threadIdx.x;
        float s = sg[o] * rsqrtf(sv[o] + 1e-5f);
        ssc[o]  = s;
        sbi[o]  = sb[o] - sm[o] * s;
    }
    __syncthreads();
    int p = blockIdx.x * 256 + threadIdx.x; // 0..131071
    int w = p & 127, h = (p >> 7) & 127, b = p >> 14;
    const float* xp = x + (size_t)b * 32 * 65536 + (h * 2) * 256 + (w * 2);
    float t[32];
#pragma unroll
    for (int o = 0; o < 32; o++) t[o] = 0.f;
#pragma unroll 4
    for (int c = 0; c < 32; c++) {
        const float* q = xp + (size_t)c * 65536;
        float pv = 0.25f * (q[0] + q[1] + q[256] + q[257]);
        const float4* wp = (const float4*)(wr + c * 32);
#pragma unroll
        for (int o4 = 0; o4 < 8; o4++) {
            float4 wv = wp[o4];
            t[4 * o4 + 0] = fmaf(pv, wv.x, t[4 * o4 + 0]);
            t[4 * o4 + 1] = fmaf(pv, wv.y, t[4 * o4 + 1]);
            t[4 * o4 + 2] = fmaf(pv, wv.z, t[4 * o4 + 2]);
            t[4 * o4 + 3] = fmaf(pv, wv.w, t[4 * o4 + 3]);
        }
    }
#pragma unroll
    for (int o = 0; o < 32; o++) t[o] = fmaxf(fmaf(t[o], ssc[o], sbi[o]), 0.f);
    float* kp = g_kmap1 + (size_t)b * 9 * 16384 + (h << 7) + w;
#pragma unroll
    for (int j = 0; j < 9; j++) {
        float acc = 0.f;
#pragma unroll
        for (int o = 0; o < 32; o++) acc = fmaf(wsp[j * 32 + o], t[o], acc);
        kp[(size_t)j * 16384] = acc;
    }
}

// ---------------------------------------------------------------------------
// K3: o1 = prelu(bn1(sum_k xi_patch * kmap1))   (stride 2, pad 1, dil 1)
// thread = (b,c,h,w) over (8,64,128,128)
// ---------------------------------------------------------------------------
__global__ __launch_bounds__(256) void k_apply1(const float* __restrict__ bg,
                                                const float* __restrict__ bb,
                                                const float* __restrict__ bm,
                                                const float* __restrict__ bv,
                                                const float* __restrict__ pr1) {
    __shared__ float sc[64], bi[64], pr[64];
    if (threadIdx.x < 64) {
        int c  = threadIdx.x;
        float s = bg[c] * rsqrtf(bv[c] + 1e-3f);
        sc[c] = s;
        bi[c] = bb[c] - bm[c] * s;
        pr[c] = pr1[c];
    }
    __syncthreads();
    int idx = blockIdx.x * 256 + threadIdx.x; // 0..8388607
    int w = idx & 127, h = (idx >> 7) & 127, c = (idx >> 14) & 63, b = idx >> 20;
    const float* kp = g_kmap1 + (size_t)b * 9 * 16384 + (h << 7) + w;
    const float* xp = g_xi + ((size_t)b * 64 + c) * 65536;
    float acc = 0.f;
#pragma unroll
    for (int ki = 0; ki < 3; ki++) {
        int r = 2 * h - 1 + ki;          // -1..255, only r<0 OOB
        if (r < 0) continue;
#pragma unroll
        for (int kj = 0; kj < 3; kj++) {
            int cc = 2 * w - 1 + kj;     // -1..255, only cc<0 OOB
            if (cc < 0) continue;
            acc = fmaf(xp[r * 256 + cc], kp[(size_t)(ki * 3 + kj) * 16384], acc);
        }
    }
    float v = fmaf(acc, sc[c], bi[c]);
    g_o1[idx] = v > 0.f ? v : pr[c] * v;
}

// ---------------------------------------------------------------------------
// K4: for each pixel, all 5 dilated branches:
//   t = relu(bn1e-5(wd_red[i] @ o1_center)); kk = wd_span[i] @ t
//   y[c] = sum_k o1[c, h+(ki-1)d, w+(kj-1)d] * kk[k]
//   out  = prelu_f(bnf(prelu_d(bnd(y))))
// block = one row of 128 pixels; weights reloaded per branch in smem
// ---------------------------------------------------------------------------
__global__ __launch_bounds__(128) void k_dil(const float* __restrict__ wd_red,
                                             const float* __restrict__ sd_g,
                                             const float* __restrict__ sd_b,
                                             const float* __restrict__ sd_m,
                                             const float* __restrict__ sd_v,
                                             const float* __restrict__ wd_span,
                                             const float* __restrict__ bnd_g,
                                             const float* __restrict__ bnd_b,
                                             const float* __restrict__ bnd_m,
                                             const float* __restrict__ bnd_v,
                                             const float* __restrict__ prd,
                                             const float* __restrict__ bnf_g,
                                             const float* __restrict__ bnf_b,
                                             const float* __restrict__ bnf_m,
                                             const float* __restrict__ bnf_v,
                                             const float* __restrict__ prf,
                                             float* __restrict__ out) {
    __shared__ float wrT[64 * 64]; // wrT[c*64+o] = wd_red[i][o][c]
    __shared__ float wsp[9 * 64];
    __shared__ float ks[64], kb[64];
    __shared__ float os_[64], ob[64], opr[64];
    __shared__ float fs[64], fb[64], fpr[64];
    const int tid = threadIdx.x;
    int pix = blockIdx.x * 128 + tid; // 0..131071
    int w = pix & 127, h = (pix >> 7) & 127, b = pix >> 14;
    const float* base = g_o1 + (size_t)b * 64 * 16384;
    const int hw = (h << 7) + w;
    const int DIL[5] = {1, 2, 4, 8, 16};
#pragma unroll 1
    for (int i = 0; i < 5; i++) {
        __syncthreads(); // protect smem reuse across branches
        for (int t = tid; t < 4096; t += 128) {
            int o = t & 63, c = t >> 6;
            wrT[t] = wd_red[i * 4096 + o * 64 + c];
        }
        for (int t = tid; t < 576; t += 128) wsp[t] = wd_span[i * 576 + t];
        if (tid < 64) {
            int c = tid, g = i * 64 + c;
            float s1 = sd_g[g] * rsqrtf(sd_v[g] + 1e-5f);
            ks[c] = s1; kb[c] = sd_b[g] - sd_m[g] * s1;
            float s2 = bnd_g[g] * rsqrtf(bnd_v[g] + 1e-3f);
            os_[c] = s2; ob[c] = bnd_b[g] - bnd_m[g] * s2; opr[c] = prd[g];
            float s3 = bnf_g[g] * rsqrtf(bnf_v[g] + 1e-3f);
            fs[c] = s3; fb[c] = bnf_b[g] - bnf_m[g] * s3; fpr[c] = prf[g];
        }
        __syncthreads();

        // ---- kernel generation: 64x64 matvec + bn(1e-5)+relu + 9x64 span ----
        float t64[64];
#pragma unroll
        for (int o = 0; o < 64; o++) t64[o] = 0.f;
#pragma unroll 2
        for (int c = 0; c < 64; c++) {
            float xc = base[(c << 14) + hw];
            const float4* wp = (const float4*)(wrT + (c << 6));
#pragma unroll
            for (int o4 = 0; o4 < 16; o4++) {
                float4 wv = wp[o4];
                t64[4 * o4 + 0] = fmaf(xc, wv.x, t64[4 * o4 + 0]);
                t64[4 * o4 + 1] = fmaf(xc, wv.y, t64[4 * o4 + 1]);
                t64[4 * o4 + 2] = fmaf(xc, wv.z, t64[4 * o4 + 2]);
                t64[4 * o4 + 3] = fmaf(xc, wv.w, t64[4 * o4 + 3]);
            }
        }
#pragma unroll
        for (int o = 0; o < 64; o++) t64[o] = fmaxf(fmaf(t64[o], ks[o], kb[o]), 0.f);
        float kk[9];
#pragma unroll
        for (int j = 0; j < 9; j++) {
            float acc = 0.f;
#pragma unroll
            for (int o = 0; o < 64; o++) acc = fmaf(wsp[j * 64 + o], t64[o], acc);
            kk[j] = acc;
        }

        // ---- apply dilated 3x3 dynamic kernel + fused epilogue ----
        int dil = DIL[i];
        int offs[9];
        bool vld[9];
#pragma unroll
        for (int ki = 0; ki < 3; ki++) {
            int r = h + (ki - 1) * dil;
            bool rok = (unsigned)r < 128u;
#pragma unroll
            for (int kj = 0; kj < 3; kj++) {
                int cc = w + (kj - 1) * dil;
                bool ok = rok && ((unsigned)cc < 128u);
                vld[ki * 3 + kj]  = ok;
                offs[ki * 3 + kj] = ok ? (r << 7) + cc : 0;
            }
        }
        float* outp = out + ((size_t)(b * 320 + i * 64) << 14) + hw;
#pragma unroll 2
        for (int c = 0; c < 64; c++) {
            const float* pc = base + (c << 14);
            float acc = 0.f;
#pragma unroll
            for (int k = 0; k < 9; k++)
                acc += vld[k] ? pc[offs[k]] * kk[k] : 0.f;
            float z = fmaf(acc, os_[c], ob[c]);
            z = z > 0.f ? z : opr[c] * z;
            float y = fmaf(z, fs[c], fb[c]);
            outp[(size_t)c << 14] = y > 0.f ? y : fpr[c] * y;
        }
    }
}

// ---------------------------------------------------------------------------
extern "C" void kernel_launch(void* const* d_in, const int* in_sizes, int n_in,
                              void* d_out, int out_size) {
    const float* x       = (const float*)d_in[0];
    const float* w1_init = (const float*)d_in[1];
    const float* w1_red  = (const float*)d_in[2];
    const float* s1_g    = (const float*)d_in[3];
    const float* s1_b    = (const float*)d_in[4];
    const float* s1_m    = (const float*)d_in[5];
    const float* s1_v    = (const float*)d_in[6];
    const float* w1_span = (const float*)d_in[7];
    const float* bn1_g   = (const float*)d_in[8];
    const float* bn1_b   = (const float*)d_in[9];
    const float* bn1_m   = (const float*)d_in[10];
    const float* bn1_v   = (const float*)d_in[11];
    const float* pr1     = (const float*)d_in[12];
    const float* wd_red  = (const float*)d_in[13];
    const float* sd_g    = (const float*)d_in[14];
    const float* sd_b    = (const float*)d_in[15];
    const float* sd_m    = (const float*)d_in[16];
    const float* sd_v    = (const float*)d_in[17];
    const float* wd_span = (const float*)d_in[18];
    const float* bnd_g   = (const float*)d_in[19];
    const float* bnd_b   = (const float*)d_in[20];
    const float* bnd_m   = (const float*)d_in[21];
    const float* bnd_v   = (const float*)d_in[22];
    const float* prd     = (const float*)d_in[23];
    const float* bnf_g   = (const float*)d_in[24];
    const float* bnf_b   = (const float*)d_in[25];
    const float* bnf_m   = (const float*)d_in[26];
    const float* bnf_v   = (const float*)d_in[27];
    const float* prf     = (const float*)d_in[28];
    float* out = (float*)d_out;

    k_xi<<<2048, 256>>>(x, w1_init);
    k_kgen1<<<512, 256>>>(x, w1_red, s1_g, s1_b, s1_m, s1_v, w1_span);
    k_apply1<<<32768, 256>>>(bn1_g, bn1_b, bn1_m, bn1_v, pr1);
    k_dil<<<1024, 128>>>(wd_red, sd_g, sd_b, sd_m, sd_v, wd_span,
                         bnd_g, bnd_b, bnd_m, bnd_v, prd,
                         bnf_g, bnf_b, bnf_m, bnf_v, prf, out);
}

// round 4
// speedup vs baseline: 1.0927x; 1.0927x over previous
#include <cuda_runtime.h>
#include <cstdint>

// ---------------------------------------------------------------------------
// DInPBlock: invo1 (32->64, s2) -> 5 dilated involutions -> concat -> bn+prelu
// Shapes: x (8,32,256,256) f32 ; out (8,320,128,128) f32
// ---------------------------------------------------------------------------

#define NBATCH 8

__device__ float g_xi[(size_t)NBATCH * 64 * 256 * 256];   // 134 MB
__device__ float g_kmap1[(size_t)NBATCH * 9 * 128 * 128];
__device__ float g_o1[(size_t)NBATCH * 64 * 128 * 128];   // 33.5 MB (L2-resident)

// ---------------------------------------------------------------------------
// K1: xi = conv1x1(x, w1_init)  (8,32,256,256) -> (8,64,256,256)
// 256 threads = 128 pixels x 2 halves; each thread 32 outputs; x row in smem
// ---------------------------------------------------------------------------
__global__ __launch_bounds__(256) void k_xi(const float* __restrict__ x,
                                            const float* __restrict__ w) {
    __shared__ float xs[32 * 128];  // xs[c*128+p]
    __shared__ float ws[32 * 64];   // ws[c*64+o] = w[o*32+c]
    const int tid = threadIdx.x;
    const int pbase = blockIdx.x * 128;          // global pixel base
    const int b = pbase >> 16;
    const int hw0 = pbase & 65535;
    for (int i = tid; i < 2048; i += 256) {
        int o = i & 63, c = i >> 6;
        ws[i] = w[o * 32 + c];
    }
    for (int i = tid; i < 4096; i += 256) {
        int p = i & 127, c = i >> 7;
        xs[i] = x[(size_t)(b * 32 + c) * 65536 + hw0 + p];
    }
    __syncthreads();
    const int p = tid & 127, half = tid >> 7;
    float acc[32];
#pragma unroll
    for (int o = 0; o < 32; o++) acc[o] = 0.f;
#pragma unroll 4
    for (int c = 0; c < 32; c++) {
        float xv = xs[(c << 7) + p];
        const float4* wp = (const float4*)(ws + (c << 6) + (half << 5));
#pragma unroll
        for (int o4 = 0; o4 < 8; o4++) {
            float4 wv = wp[o4];
            acc[4 * o4 + 0] = fmaf(xv, wv.x, acc[4 * o4 + 0]);
            acc[4 * o4 + 1] = fmaf(xv, wv.y, acc[4 * o4 + 1]);
            acc[4 * o4 + 2] = fmaf(xv, wv.z, acc[4 * o4 + 2]);
            acc[4 * o4 + 3] = fmaf(xv, wv.w, acc[4 * o4 + 3]);
        }
    }
    float* op = g_xi + (size_t)(b * 64 + half * 32) * 65536 + hw0 + p;
#pragma unroll
    for (int o = 0; o < 32; o++) op[(size_t)o * 65536] = acc[o];
}

// ---------------------------------------------------------------------------
// K2: invo1 kernel map: avgpool2x2(x) -> 32->32 -> bn(1e-5)+relu -> 32->9
// ---------------------------------------------------------------------------
__global__ __launch_bounds__(256) void k_kgen1(const float* __restrict__ x,
                                               const float* __restrict__ wred,
                                               const float* __restrict__ sg,
                                               const float* __restrict__ sb,
                                               const float* __restrict__ sm,
                                               const float* __restrict__ sv,
                                               const float* __restrict__ wspan) {
    __shared__ float wr[32 * 32];
    __shared__ float wsp[9 * 32];
    __shared__ float ssc[32], sbi[32];
    for (int i = threadIdx.x; i < 1024; i += 256) {
        int o = i & 31, c = i >> 5;
        wr[i] = wred[o * 32 + c];
    }
    for (int i = threadIdx.x; i < 288; i += 256) wsp[i] = wspan[i];
    if (threadIdx.x < 32) {
        int o = threadIdx.x;
        float s = sg[o] * rsqrtf(sv[o] + 1e-5f);
        ssc[o] = s;
        sbi[o] = sb[o] - sm[o] * s;
    }
    __syncthreads();
    int p = blockIdx.x * 256 + threadIdx.x;
    int w = p & 127, h = (p >> 7) & 127, b = p >> 14;
    const float* xp = x + (size_t)b * 32 * 65536 + (h * 2) * 256 + (w * 2);
    float t[32];
#pragma unroll
    for (int o = 0; o < 32; o++) t[o] = 0.f;
#pragma unroll 4
    for (int c = 0; c < 32; c++) {
        const float* q = xp + (size_t)c * 65536;
        float pv = 0.25f * (q[0] + q[1] + q[256] + q[257]);
        const float4* wp = (const float4*)(wr + c * 32);
#pragma unroll
        for (int o4 = 0; o4 < 8; o4++) {
            float4 wv = wp[o4];
            t[4 * o4 + 0] = fmaf(pv, wv.x, t[4 * o4 + 0]);
            t[4 * o4 + 1] = fmaf(pv, wv.y, t[4 * o4 + 1]);
            t[4 * o4 + 2] = fmaf(pv, wv.z, t[4 * o4 + 2]);
            t[4 * o4 + 3] = fmaf(pv, wv.w, t[4 * o4 + 3]);
        }
    }
#pragma unroll
    for (int o = 0; o < 32; o++) t[o] = fmaxf(fmaf(t[o], ssc[o], sbi[o]), 0.f);
    float* kp = g_kmap1 + (size_t)b * 9 * 16384 + (h << 7) + w;
#pragma unroll
    for (int j = 0; j < 9; j++) {
        float acc = 0.f;
#pragma unroll
        for (int o = 0; o < 32; o++) acc = fmaf(wsp[j * 32 + o], t[o], acc);
        kp[(size_t)j * 16384] = acc;
    }
}

// ---------------------------------------------------------------------------
// K3: o1 = prelu(bn1(sum_k xi_patch * kmap1))  (stride 2, pad 1)
// 4 channels per thread (amortize kmap loads)
// ---------------------------------------------------------------------------
__global__ __launch_bounds__(256) void k_apply1(const float* __restrict__ bg,
                                                const float* __restrict__ bb,
                                                const float* __restrict__ bm,
                                                const float* __restrict__ bv,
                                                const float* __restrict__ pr1) {
    __shared__ float sc[64], bi[64], pr[64];
    if (threadIdx.x < 64) {
        int c = threadIdx.x;
        float s = bg[c] * rsqrtf(bv[c] + 1e-3f);
        sc[c] = s;
        bi[c] = bb[c] - bm[c] * s;
        pr[c] = pr1[c];
    }
    __syncthreads();
    int idx = blockIdx.x * 256 + threadIdx.x;  // 0..2097151
    int w = idx & 127, h = (idx >> 7) & 127, c4 = (idx >> 14) & 15, b = idx >> 18;
    const float* kp = g_kmap1 + (size_t)b * 9 * 16384 + (h << 7) + w;
    float kv[9];
    int roff[9];
    unsigned vmask = 0;
#pragma unroll
    for (int ki = 0; ki < 3; ki++) {
        int r = 2 * h - 1 + ki;
#pragma unroll
        for (int kj = 0; kj < 3; kj++) {
            int cc = 2 * w - 1 + kj;
            int k = ki * 3 + kj;
            kv[k] = kp[(size_t)k * 16384];
            bool ok = (r >= 0) && (cc >= 0);
            if (ok) vmask |= (1u << k);
            roff[k] = ok ? r * 256 + cc : 0;
        }
    }
#pragma unroll
    for (int q = 0; q < 4; q++) {
        int c = c4 * 4 + q;
        const float* xp = g_xi + ((size_t)b * 64 + c) * 65536;
        float acc = 0.f;
#pragma unroll
        for (int k = 0; k < 9; k++)
            if (vmask & (1u << k)) acc = fmaf(xp[roff[k]], kv[k], acc);
        float v = fmaf(acc, sc[c], bi[c]);
        g_o1[((size_t)(b * 64 + c) << 14) + (h << 7) + w] = v > 0.f ? v : pr[c] * v;
    }
}

// ---------------------------------------------------------------------------
// K4: one block = one (branch, row, batch). 256 threads = 128 px x 2 halves.
// Center row staged in smem; span partials exchanged via smem.
// ---------------------------------------------------------------------------
__global__ __launch_bounds__(256) void k_dil(const float* __restrict__ wd_red,
                                             const float* __restrict__ sd_g,
                                             const float* __restrict__ sd_b,
                                             const float* __restrict__ sd_m,
                                             const float* __restrict__ sd_v,
                                             const float* __restrict__ wd_span,
                                             const float* __restrict__ bnd_g,
                                             const float* __restrict__ bnd_b,
                                             const float* __restrict__ bnd_m,
                                             const float* __restrict__ bnd_v,
                                             const float* __restrict__ prd,
                                             const float* __restrict__ bnf_g,
                                             const float* __restrict__ bnf_b,
                                             const float* __restrict__ bnf_m,
                                             const float* __restrict__ bnf_v,
                                             const float* __restrict__ prf,
                                             float* __restrict__ out) {
    __shared__ float cs[64 * 128];    // center row: cs[c*128+p]
    __shared__ float wrT[64 * 64];    // wrT[c*64+o]
    __shared__ float wsp[9 * 64];
    __shared__ float part[2 * 9 * 128];
    __shared__ float ks[64], kb[64], os_[64], ob[64], opr[64], fs[64], fb[64], fpr[64];
    const int i = blockIdx.x;   // branch 0..4
    const int h = blockIdx.y;   // row 0..127
    const int b = blockIdx.z;   // batch 0..7
    const int tid = threadIdx.x;
    const int pix = tid & 127, half = tid >> 7;
    const float* base = g_o1 + (size_t)b * 64 * 16384;

    for (int t = tid; t < 8192; t += 256) {
        int c = t >> 7, p = t & 127;
        cs[t] = base[(c << 14) + (h << 7) + p];
    }
    for (int t = tid; t < 4096; t += 256) {
        int o = t & 63, c = t >> 6;
        wrT[t] = wd_red[i * 4096 + o * 64 + c];
    }
    for (int t = tid; t < 576; t += 256) wsp[t] = wd_span[i * 576 + t];
    if (tid < 64) {
        int c = tid, g = i * 64 + c;
        float s1 = sd_g[g] * rsqrtf(sd_v[g] + 1e-5f);
        ks[c] = s1; kb[c] = sd_b[g] - sd_m[g] * s1;
        float s2 = bnd_g[g] * rsqrtf(bnd_v[g] + 1e-3f);
        os_[c] = s2; ob[c] = bnd_b[g] - bnd_m[g] * s2; opr[c] = prd[g];
        float s3 = bnf_g[g] * rsqrtf(bnf_v[g] + 1e-3f);
        fs[c] = s3; fb[c] = bnf_b[g] - bnf_m[g] * s3; fpr[c] = prf[g];
    }
    __syncthreads();

    // ---- 64x64 matvec (this thread: 32 outputs) ----
    float acc[32];
#pragma unroll
    for (int o = 0; o < 32; o++) acc[o] = 0.f;
#pragma unroll 4
    for (int c = 0; c < 64; c++) {
        float xc = cs[(c << 7) + pix];
        const float4* wp = (const float4*)(wrT + (c << 6) + (half << 5));
#pragma unroll
        for (int o4 = 0; o4 < 8; o4++) {
            float4 wv = wp[o4];
            acc[4 * o4 + 0] = fmaf(xc, wv.x, acc[4 * o4 + 0]);
            acc[4 * o4 + 1] = fmaf(xc, wv.y, acc[4 * o4 + 1]);
            acc[4 * o4 + 2] = fmaf(xc, wv.z, acc[4 * o4 + 2]);
            acc[4 * o4 + 3] = fmaf(xc, wv.w, acc[4 * o4 + 3]);
        }
    }
#pragma unroll
    for (int j = 0; j < 32; j++) {
        int o = (half << 5) + j;
        acc[j] = fmaxf(fmaf(acc[j], ks[o], kb[o]), 0.f);
    }
    // ---- span partials (9 x 32) ----
#pragma unroll
    for (int j = 0; j < 9; j++) {
        float s = 0.f;
#pragma unroll
        for (int l = 0; l < 32; l++) s = fmaf(wsp[j * 64 + (half << 5) + l], acc[l], s);
        part[((half * 9 + j) << 7) + pix] = s;
    }
    __syncthreads();
    float kk[9];
#pragma unroll
    for (int j = 0; j < 9; j++) kk[j] = part[(j << 7) + pix] + part[((9 + j) << 7) + pix];

    // ---- dilated 3x3 apply + fused epilogue (32 channels) ----
    const int dil = 1 << i;
    int offs[9];
    unsigned vmask = 0;
#pragma unroll
    for (int ki = 0; ki < 3; ki++) {
        int r = h + (ki - 1) * dil;
        bool rok = (unsigned)r < 128u;
#pragma unroll
        for (int kj = 0; kj < 3; kj++) {
            int cc = pix + (kj - 1) * dil;
            bool ok = rok && ((unsigned)cc < 128u);
            int k = ki * 3 + kj;
            if (ok) vmask |= (1u << k);
            offs[k] = ok ? (r << 7) + cc : 0;
        }
    }
    float* outp = out + ((size_t)(b * 320 + i * 64 + (half << 5)) << 14) + (h << 7) + pix;
#pragma unroll 2
    for (int cl = 0; cl < 32; cl++) {
        int c = (half << 5) + cl;
        const float* pc = base + ((size_t)c << 14);
        float a = 0.f;
#pragma unroll
        for (int k = 0; k < 9; k++)
            if (vmask & (1u << k)) a = fmaf(__ldg(pc + offs[k]), kk[k], a);
        float z = fmaf(a, os_[c], ob[c]);
        z = z > 0.f ? z : opr[c] * z;
        float y = fmaf(z, fs[c], fb[c]);
        outp[(size_t)cl << 14] = y > 0.f ? y : fpr[c] * y;
    }
}

// ---------------------------------------------------------------------------
extern "C" void kernel_launch(void* const* d_in, const int* in_sizes, int n_in,
                              void* d_out, int out_size) {
    const float* x       = (const float*)d_in[0];
    const float* w1_init = (const float*)d_in[1];
    const float* w1_red  = (const float*)d_in[2];
    const float* s1_g    = (const float*)d_in[3];
    const float* s1_b    = (const float*)d_in[4];
    const float* s1_m    = (const float*)d_in[5];
    const float* s1_v    = (const float*)d_in[6];
    const float* w1_span = (const float*)d_in[7];
    const float* bn1_g   = (const float*)d_in[8];
    const float* bn1_b   = (const float*)d_in[9];
    const float* bn1_m   = (const float*)d_in[10];
    const float* bn1_v   = (const float*)d_in[11];
    const float* pr1     = (const float*)d_in[12];
    const float* wd_red  = (const float*)d_in[13];
    const float* sd_g    = (const float*)d_in[14];
    const float* sd_b    = (const float*)d_in[15];
    const float* sd_m    = (const float*)d_in[16];
    const float* sd_v    = (const float*)d_in[17];
    const float* wd_span = (const float*)d_in[18];
    const float* bnd_g   = (const float*)d_in[19];
    const float* bnd_b   = (const float*)d_in[20];
    const float* bnd_m   = (const float*)d_in[21];
    const float* bnd_v   = (const float*)d_in[22];
    const float* prd     = (const float*)d_in[23];
    const float* bnf_g   = (const float*)d_in[24];
    const float* bnf_b   = (const float*)d_in[25];
    const float* bnf_m   = (const float*)d_in[26];
    const float* bnf_v   = (const float*)d_in[27];
    const float* prf     = (const float*)d_in[28];
    float* out = (float*)d_out;

    k_xi<<<4096, 256>>>(x, w1_init);
    k_kgen1<<<512, 256>>>(x, w1_red, s1_g, s1_b, s1_m, s1_v, w1_span);
    k_apply1<<<8192, 256>>>(bn1_g, bn1_b, bn1_m, bn1_v, pr1);
    k_dil<<<dim3(5, 128, 8), 256>>>(wd_red, sd_g, sd_b, sd_m, sd_v, wd_span,
                                    bnd_g, bnd_b, bnd_m, bnd_v, prd,
                                    bnf_g, bnf_b, bnf_m, bnf_v, prf, out);
}